// round 1
// baseline (speedup 1.0000x reference)
#include <cuda_runtime.h>
#include <math.h>

#define BB 2
#define VV 3
#define CC 32
#define DD 32
#define HH 96
#define WW 128

// Scratch (static __device__ arrays; no allocation anywhere)
__device__ float g_RT[BB * VV * 12];                         // per (b,v): R(9), t(3)
__device__ float g_var[(size_t)BB * DD * CC * HH * WW];      // (B, D, C, H, W)  ~100.7 MB
__device__ float g_u[(size_t)BB * 3 * DD * HH * WW];         // (B, zz, D, H, W) ~9.4 MB

// ---------------------------------------------------------------------------
// Setup: per (b, src view v>=1) compute R = A_src * inv(A_ref), t = a_src - R*a_ref
// where composed = [A | a; 0 0 0 1], A = K3 @ E[:3,:3], a = K3 @ E[:3,3].
// ---------------------------------------------------------------------------
__global__ void k_setup(const float* __restrict__ proj) {
    int t = threadIdx.x;
    if (t >= BB * (VV - 1)) return;
    int b = t / (VV - 1);
    int v = 1 + t % (VV - 1);

    const float* Eref = proj + ((size_t)(b * VV + 0) * 2 + 0) * 16;
    const float* Kref = proj + ((size_t)(b * VV + 0) * 2 + 1) * 16;
    const float* Es   = proj + ((size_t)(b * VV + v) * 2 + 0) * 16;
    const float* Ks   = proj + ((size_t)(b * VV + v) * 2 + 1) * 16;

    float Ar[9], ar[3], As[9], asv[3];
    for (int i = 0; i < 3; i++) {
        for (int j = 0; j < 3; j++) {
            float s = 0.f, s2 = 0.f;
            for (int k = 0; k < 3; k++) {
                s  += Kref[i * 4 + k] * Eref[k * 4 + j];
                s2 += Ks[i * 4 + k]   * Es[k * 4 + j];
            }
            Ar[i * 3 + j] = s;
            As[i * 3 + j] = s2;
        }
        float s = 0.f, s2 = 0.f;
        for (int k = 0; k < 3; k++) {
            s  += Kref[i * 4 + k] * Eref[k * 4 + 3];
            s2 += Ks[i * 4 + k]   * Es[k * 4 + 3];
        }
        ar[i] = s;
        asv[i] = s2;
    }

    // 3x3 inverse of Ar (adjugate / det)
    float det = Ar[0] * (Ar[4] * Ar[8] - Ar[5] * Ar[7])
              - Ar[1] * (Ar[3] * Ar[8] - Ar[5] * Ar[6])
              + Ar[2] * (Ar[3] * Ar[7] - Ar[4] * Ar[6]);
    float id = 1.0f / det;
    float Ai[9];
    Ai[0] = (Ar[4] * Ar[8] - Ar[5] * Ar[7]) * id;
    Ai[1] = (Ar[2] * Ar[7] - Ar[1] * Ar[8]) * id;
    Ai[2] = (Ar[1] * Ar[5] - Ar[2] * Ar[4]) * id;
    Ai[3] = (Ar[5] * Ar[6] - Ar[3] * Ar[8]) * id;
    Ai[4] = (Ar[0] * Ar[8] - Ar[2] * Ar[6]) * id;
    Ai[5] = (Ar[2] * Ar[3] - Ar[0] * Ar[5]) * id;
    Ai[6] = (Ar[3] * Ar[7] - Ar[4] * Ar[6]) * id;
    Ai[7] = (Ar[1] * Ar[6] - Ar[0] * Ar[7]) * id;
    Ai[8] = (Ar[0] * Ar[4] - Ar[1] * Ar[3]) * id;

    float R[9], tt[3];
    for (int i = 0; i < 3; i++)
        for (int j = 0; j < 3; j++) {
            float s = 0.f;
            for (int k = 0; k < 3; k++) s += As[i * 3 + k] * Ai[k * 3 + j];
            R[i * 3 + j] = s;
        }
    for (int i = 0; i < 3; i++) {
        float s = 0.f;
        for (int k = 0; k < 3; k++) s += R[i * 3 + k] * ar[k];
        tt[i] = asv[i] - s;
    }

    float* out = g_RT + (size_t)(b * VV + v) * 12;
    for (int i = 0; i < 9; i++) out[i] = R[i];
    for (int i = 0; i < 3; i++) out[9 + i] = tt[i];
}

// ---------------------------------------------------------------------------
// Kernel 1: homography warp + bilinear + running variance over 3 views.
// One thread per (b,d,h,w); lanes map to w -> coalesced fea reads & var writes.
// var layout: (B, D, C, H, W).
// ---------------------------------------------------------------------------
__global__ __launch_bounds__(256) void k_warpvar(const float* __restrict__ fea,
                                                 const float* __restrict__ depthv) {
    int tid = blockIdx.x * blockDim.x + threadIdx.x;   // exact grid: B*D*H*W
    int w = tid & (WW - 1);
    int h = (tid / WW) % HH;
    int d = (tid / (WW * HH)) % DD;
    int b = tid / (WW * HH * DD);

    float dval = depthv[tid];   // depth_values has the same (B,D,H,W) layout

    int   cofs[2][4];
    float cw[2][4];
    #pragma unroll
    for (int vi = 0; vi < 2; vi++) {
        const float* rt = g_RT + (size_t)(b * VV + (vi + 1)) * 12;
        float fw = (float)w, fh = (float)h;
        float X = (rt[0] * fw + rt[1] * fh + rt[2]) * dval + rt[9];
        float Y = (rt[3] * fw + rt[4] * fh + rt[5]) * dval + rt[10];
        float Z = (rt[6] * fw + rt[7] * fh + rt[8]) * dval + rt[11];
        float px = X / Z;
        float py = Y / Z;
        float x0f = floorf(px), y0f = floorf(py);
        float fx = px - x0f, fy = py - y0f;
        float wx[2] = {1.0f - fx, fx};
        float wy[2] = {1.0f - fy, fy};
        float xi[2] = {x0f, x0f + 1.0f};
        float yi[2] = {y0f, y0f + 1.0f};
        bool vx[2] = {xi[0] >= 0.0f && xi[0] <= (float)(WW - 1),
                      xi[1] >= 0.0f && xi[1] <= (float)(WW - 1)};
        bool vy[2] = {yi[0] >= 0.0f && yi[0] <= (float)(HH - 1),
                      yi[1] >= 0.0f && yi[1] <= (float)(HH - 1)};
        int xc[2] = {min(max((int)xi[0], 0), WW - 1), min(max((int)xi[1], 0), WW - 1)};
        int yc[2] = {min(max((int)yi[0], 0), HH - 1), min(max((int)yi[1], 0), HH - 1)};
        #pragma unroll
        for (int k = 0; k < 4; k++) {
            int dx = k & 1, dy = k >> 1;
            float wgt = wx[dx] * wy[dy];
            if (!(vx[dx] && vy[dy])) wgt = 0.0f;
            cw[vi][k] = wgt;
            cofs[vi][k] = yc[dy] * WW + xc[dx];
        }
    }

    const size_t plane = (size_t)HH * WW;
    const float* feaRef = fea + (size_t)(b * VV + 0) * CC * plane + (size_t)h * WW + w;
    const float* feaS0  = fea + (size_t)(b * VV + 1) * CC * plane;
    const float* feaS1  = fea + (size_t)(b * VV + 2) * CC * plane;
    float* varBase = g_var + (size_t)(b * DD + d) * CC * plane + (size_t)h * WW + w;

    #pragma unroll 4
    for (int c = 0; c < CC; c++) {
        size_t co = (size_t)c * plane;
        float r = feaRef[co];
        float s = r, q = r * r;

        const float* f0 = feaS0 + co;
        float wa0 = cw[0][0] * f0[cofs[0][0]] + cw[0][1] * f0[cofs[0][1]]
                  + cw[0][2] * f0[cofs[0][2]] + cw[0][3] * f0[cofs[0][3]];
        s += wa0; q += wa0 * wa0;

        const float* f1 = feaS1 + co;
        float wa1 = cw[1][0] * f1[cofs[1][0]] + cw[1][1] * f1[cofs[1][1]]
                  + cw[1][2] * f1[cofs[1][2]] + cw[1][3] * f1[cofs[1][3]];
        s += wa1; q += wa1 * wa1;

        float sm = s * (1.0f / 3.0f);
        varBase[co] = q * (1.0f / 3.0f) - sm * sm;
    }
}

// ---------------------------------------------------------------------------
// Kernel 2: per var slice dd, compute the three depth-tap partial 2D convs:
//   u_zz(b,dd,h,w) = sum_{c,dy,dx} w_reg[c,zz,dy,dx] * var[b,dd,c,h+dy-1,w+dx-1]
// Each thread produces 4 consecutive-w outputs (row-window reuse).
// ---------------------------------------------------------------------------
__global__ __launch_bounds__(128) void k_conv_u(const float* __restrict__ wreg) {
    __shared__ float sh_w[27 * 32];   // [ (zz*3+dy)*3+dx ][ c ]
    int tid = threadIdx.x;
    for (int i = tid; i < 864; i += blockDim.x) {
        int c = i / 27, r = i % 27;
        sh_w[r * 32 + c] = wreg[i];
    }
    __syncthreads();

    int gid = blockIdx.x * blockDim.x + tid;   // exact grid: B*D*H*(W/4)
    int wi = gid & 31;
    int w0 = wi * 4;
    int rest = gid >> 5;
    int h  = rest % HH;
    int dd = (rest / HH) % DD;
    int b  = rest / (HH * DD);

    float u0a = 0.f, u0b = 0.f, u0c = 0.f, u0d = 0.f;
    float u1a = 0.f, u1b = 0.f, u1c = 0.f, u1d = 0.f;
    float u2a = 0.f, u2b = 0.f, u2c = 0.f, u2d = 0.f;

    const size_t plane = (size_t)HH * WW;
    const float* sbase = g_var + (size_t)(b * DD + dd) * CC * plane;

    #pragma unroll
    for (int dy = 0; dy < 3; dy++) {
        int hy = h + dy - 1;
        if ((unsigned)hy >= (unsigned)HH) continue;
        #pragma unroll 4
        for (int c = 0; c < CC; c++) {
            const float* row = sbase + (size_t)c * plane + (size_t)hy * WW;
            float xm = (w0 > 0) ? row[w0 - 1] : 0.0f;
            float4 v4 = *reinterpret_cast<const float4*>(row + w0);
            float xp = (w0 + 4 < WW) ? row[w0 + 4] : 0.0f;
            float x0 = xm, x1 = v4.x, x2 = v4.y, x3 = v4.z, x4 = v4.w, x5 = xp;

            {
                float wA = sh_w[((0 * 3 + dy) * 3 + 0) * 32 + c];
                float wB = sh_w[((0 * 3 + dy) * 3 + 1) * 32 + c];
                float wC = sh_w[((0 * 3 + dy) * 3 + 2) * 32 + c];
                u0a += wA * x0 + wB * x1 + wC * x2;
                u0b += wA * x1 + wB * x2 + wC * x3;
                u0c += wA * x2 + wB * x3 + wC * x4;
                u0d += wA * x3 + wB * x4 + wC * x5;
            }
            {
                float wA = sh_w[((1 * 3 + dy) * 3 + 0) * 32 + c];
                float wB = sh_w[((1 * 3 + dy) * 3 + 1) * 32 + c];
                float wC = sh_w[((1 * 3 + dy) * 3 + 2) * 32 + c];
                u1a += wA * x0 + wB * x1 + wC * x2;
                u1b += wA * x1 + wB * x2 + wC * x3;
                u1c += wA * x2 + wB * x3 + wC * x4;
                u1d += wA * x3 + wB * x4 + wC * x5;
            }
            {
                float wA = sh_w[((2 * 3 + dy) * 3 + 0) * 32 + c];
                float wB = sh_w[((2 * 3 + dy) * 3 + 1) * 32 + c];
                float wC = sh_w[((2 * 3 + dy) * 3 + 2) * 32 + c];
                u2a += wA * x0 + wB * x1 + wC * x2;
                u2b += wA * x1 + wB * x2 + wC * x3;
                u2c += wA * x2 + wB * x3 + wC * x4;
                u2d += wA * x3 + wB * x4 + wC * x5;
            }
        }
    }

    size_t obase = (((size_t)b * 3 + 0) * DD + dd) * plane + (size_t)h * WW + w0;
    size_t zstep = (size_t)DD * plane;
    *reinterpret_cast<float4*>(g_u + obase)             = make_float4(u0a, u0b, u0c, u0d);
    *reinterpret_cast<float4*>(g_u + obase + zstep)     = make_float4(u1a, u1b, u1c, u1d);
    *reinterpret_cast<float4*>(g_u + obase + 2 * zstep) = make_float4(u2a, u2b, u2c, u2d);
}

// ---------------------------------------------------------------------------
// Kernel 3: pre[d] = u0[d-1] + u1[d] + u2[d+1]; softmax over D; expected depth;
// confidence = sum p[idx-1..idx+2], idx = trunc(sum p*d) clamped.
// (b_reg shift cancels in softmax.)
// ---------------------------------------------------------------------------
__global__ __launch_bounds__(128) void k_final(const float* __restrict__ depthv,
                                               float* __restrict__ out) {
    int gid = blockIdx.x * blockDim.x + threadIdx.x;   // B*H*W
    if (gid >= BB * HH * WW) return;
    int w = gid & (WW - 1);
    int h = (gid / WW) % HH;
    int b = gid / (WW * HH);

    const size_t plane = (size_t)HH * WW;
    size_t pix = (size_t)h * WW + w;
    const float* u0 = g_u + ((size_t)b * 3 + 0) * DD * plane + pix;
    const float* u1 = g_u + ((size_t)b * 3 + 1) * DD * plane + pix;
    const float* u2 = g_u + ((size_t)b * 3 + 2) * DD * plane + pix;

    float pre[DD];
    #pragma unroll
    for (int d = 0; d < DD; d++) {
        float v = u1[(size_t)d * plane];
        if (d > 0)      v += u0[(size_t)(d - 1) * plane];
        if (d < DD - 1) v += u2[(size_t)(d + 1) * plane];
        pre[d] = v;
    }

    float m = pre[0];
    #pragma unroll
    for (int d = 1; d < DD; d++) m = fmaxf(m, pre[d]);

    float s = 0.f;
    #pragma unroll
    for (int d = 0; d < DD; d++) {
        float e = expf(pre[d] - m);
        pre[d] = e;
        s += e;
    }
    float inv = 1.0f / s;

    const float* dv = depthv + (size_t)b * DD * plane + pix;
    float depth = 0.f, sidx = 0.f;
    #pragma unroll
    for (int d = 0; d < DD; d++) {
        float p = pre[d] * inv;
        pre[d] = p;
        depth += p * dv[(size_t)d * plane];
        sidx  += p * (float)d;
    }

    int idx = (int)sidx;
    if (idx < 0) idx = 0;
    if (idx > DD - 1) idx = DD - 1;

    float conf = 0.f;
    #pragma unroll
    for (int d = 0; d < DD; d++) {
        if (d >= idx - 1 && d <= idx + 2) conf += pre[d];
    }

    out[gid] = depth;
    out[BB * HH * WW + gid] = conf;
}

// ---------------------------------------------------------------------------
extern "C" void kernel_launch(void* const* d_in, const int* in_sizes, int n_in,
                              void* d_out, int out_size) {
    const float* features = (const float*)d_in[0];   // (B,V,C,H,W)
    const float* proj     = (const float*)d_in[1];   // (B,V,2,4,4)
    const float* depthv   = (const float*)d_in[2];   // (B,D,H,W)
    const float* wreg     = (const float*)d_in[3];   // (1,C,3,3,3)
    // d_in[4] = b_reg: cancels in softmax, unused
    float* out = (float*)d_out;

    k_setup<<<1, 32>>>(proj);
    k_warpvar<<<(BB * DD * HH * WW) / 256, 256>>>(features, depthv);
    k_conv_u<<<(BB * DD * HH * (WW / 4)) / 128, 128>>>(wreg);
    k_final<<<(BB * HH * WW + 127) / 128, 128>>>(depthv, out);
}